// round 15
// baseline (speedup 1.0000x reference)
#include <cuda_runtime.h>

typedef unsigned long long ull;

constexpr int BS = 16384, D = 100, H = 16, P = 2;
constexpr int TB_B = 128;     // batch per block (8 warps x 4 bq x 4 b)
constexpr int TB_T = 8;       // t per block
constexpr int NTH  = 256;     // 8 warps
constexpr int W0S  = 1604;    // sW0 row stride floats (401 f4)
constexpr int W1S  = 260;

// smem map (float offsets)
constexpr int OFF_W0 = 0;                       // 8*1604 = 12832
constexpr int OFF_X  = OFF_W0 + 8 * W0S;        // 12832 ; 100*128 = 12800
constexpr int OFF_W1 = OFF_X  + 12800;          // 25632 ; 2080
constexpr int OFF_B1 = OFF_W1 + 8 * W1S;        // 27712 ; 144
constexpr int OFF_W2 = OFF_B1 + 144;            // 27856 ; 288
constexpr int OFF_B2 = OFF_W2 + 288;            // 28144 ; 16
constexpr int SMEM_FLOATS = OFF_B2 + 16;        // 28160 -> 112640 B (1 CTA/SM)

__device__ __forceinline__ ull pk2(float a, float b) {
    ull r; asm("mov.b64 %0, {%1, %2};" : "=l"(r) : "f"(a), "f"(b)); return r;
}
__device__ __forceinline__ void unpk2(ull v, float& a, float& b) {
    asm("mov.b64 {%0, %1}, %2;" : "=f"(a), "=f"(b) : "l"(v));
}
__device__ __forceinline__ ull ffma2(ull a, ull b, ull c) {
    ull d; asm("fma.rn.f32x2 %0, %1, %2, %3;" : "=l"(d) : "l"(a), "l"(b), "l"(c));
    return d;
}
__device__ __forceinline__ float lrelu(float v) { return v > 0.f ? v : 0.01f * v; }

__global__ void __launch_bounds__(NTH, 1)
mlp_kernel(const float* __restrict__ xg, const float* __restrict__ M,
           const float* __restrict__ W0g, const float* __restrict__ W1g,
           const float* __restrict__ W2g, const float* __restrict__ b0g,
           const float* __restrict__ b1g, const float* __restrict__ b2g,
           float* __restrict__ out) {
    extern __shared__ float smem[];
    float* sW0 = smem + OFF_W0;
    float* sX  = smem + OFF_X;
    float* sW1 = smem + OFF_W1;
    float* sB1 = smem + OFF_B1;
    float* sW2 = smem + OFF_W2;
    float* sB2 = smem + OFF_B2;

    const int tid  = threadIdx.x;
    const int lane = tid & 31, w = tid >> 5;
    const int tl = lane & 7, bq = lane >> 3;
    const int t0 = blockIdx.x * TB_T;          // t tiles on fast grid dim
    const int t  = t0 + tl;
    const bool tv = (t < D);
    const int tc = tv ? t : (D - 1);
    const int Bb    = blockIdx.y * TB_B;
    const int bloc  = w * 16 + bq * 4;         // this thread: local b .. b+3
    const int Bbase = Bb + bloc;

    // ---- stage W0 tile, transposing [t][i][j] -> sW0[r][j][i] ----
    for (int e = tid; e < 4096; e += NTH) {
        int i4 = e & 3, jql = (e >> 2) & 7, jqh = (e >> 5) & 3;
        int ih = (e >> 7) & 3, r = (e >> 9) & 7;
        int jq = jql + 8 * jqh, i = i4 + 4 * ih;
        if (jq < 25) {
            int tt = t0 + r;
            float4 v = make_float4(0.f, 0.f, 0.f, 0.f);
            if (tt < D)
                v = *(const float4*)(W0g + ((size_t)(tt * H + i)) * D + 4 * jq);
            float* dst = sW0 + r * W0S + i;
            dst[(4 * jq + 0) * 16] = v.x;
            dst[(4 * jq + 1) * 16] = v.y;
            dst[(4 * jq + 2) * 16] = v.z;
            dst[(4 * jq + 3) * 16] = v.w;
        }
    }
    // ---- stage x tile, transposing x[b][j] -> sX[j][b] (128 b wide) ----
    for (int e = tid; e < 3200; e += NTH) {
        int b = e & 127, jq = e >> 7;          // jq 0..24
        float4 v = *(const float4*)(xg + (size_t)(Bb + b) * D + 4 * jq);
        sX[(4 * jq + 0) * 128 + b] = v.x;
        sX[(4 * jq + 1) * 128 + b] = v.y;
        sX[(4 * jq + 2) * 128 + b] = v.z;
        sX[(4 * jq + 3) * 128 + b] = v.w;
    }
    for (int e = tid; e < 8 * 256; e += NTH) {               // W1 direct copy
        int r = e >> 8, c = e & 255;
        sW1[r * W1S + c] = (t0 + r < D) ? W1g[(t0 + r) * 256 + c] : 0.f;
    }
    if (tid < 128) {
        int r = tid >> 4, c = tid & 15;
        sB1[r * 17 + c] = (t0 + r < D) ? b1g[(t0 + r) * H + c] : 0.f;
    }
    if (tid < 256) {
        int r = tid >> 5, c = tid & 31;
        sW2[r * 36 + c] = (t0 + r < D) ? W2g[(t0 + r) * (P * H) + c] : 0.f;
    }
    if (tid < 16) {
        int r = tid >> 1, c = tid & 1;
        sB2[r * 2 + c] = (t0 + r < D) ? b2g[(t0 + r) * P + c] : 0.f;
    }
    __syncthreads();

    // ---- acc init with b0 (acc[u][ip], u = 4 owned b) ----
    ull acc[4][8];
#pragma unroll
    for (int ip = 0; ip < 8; ++ip) {
        float a = tv ? __ldg(b0g + t * H + 2 * ip)     : 0.f;
        float b = tv ? __ldg(b0g + t * H + 2 * ip + 1) : 0.f;
        ull bb = pk2(a, b);
        acc[0][ip] = bb; acc[1][ip] = bb; acc[2][ip] = bb; acc[3][ip] = bb;
    }

    const float* mp = M + (size_t)Bbase * (D * D) + tc;

    // 3-buffer register pipeline: chunk = 2 j x 4 b, distance = 2 chunks
    float m[3][2][4];

#define LOAD_CHUNK(cn, buf)                                                     \
    if ((cn) < 50) {                                                            \
        _Pragma("unroll")                                                       \
        for (int jj = 0; jj < 2; ++jj) {                                        \
            int j = (cn) * 2 + jj;                                              \
            m[buf][jj][0] = __ldg(mp + j * D);                                  \
            m[buf][jj][1] = __ldg(mp + j * D + 1 * D * D);                      \
            m[buf][jj][2] = __ldg(mp + j * D + 2 * D * D);                      \
            m[buf][jj][3] = __ldg(mp + j * D + 3 * D * D);                      \
        }                                                                       \
    }

#define COMP_CHUNK(cn, buf)                                                     \
    {                                                                           \
        _Pragma("unroll")                                                       \
        for (int jj = 0; jj < 2; ++jj) {                                        \
            int j = (cn) * 2 + jj;                                              \
            float4 x4 = *(const float4*)(sX + j * 128 + bloc);                  \
            const longlong2* wr = (const longlong2*)(sW0 + tl * W0S + j * 16);  \
            longlong2 q0 = wr[0], q1 = wr[1], q2 = wr[2], q3 = wr[3];           \
            ull W[8] = {(ull)q0.x, (ull)q0.y, (ull)q1.x, (ull)q1.y,             \
                        (ull)q2.x, (ull)q2.y, (ull)q3.x, (ull)q3.y};            \
            float mx0 = m[buf][jj][0] * x4.x;                                   \
            float mx1 = m[buf][jj][1] * x4.y;                                   \
            float mx2 = m[buf][jj][2] * x4.z;                                   \
            float mx3 = m[buf][jj][3] * x4.w;                                   \
            ull p0 = pk2(mx0, mx0), p1 = pk2(mx1, mx1);                         \
            ull p2 = pk2(mx2, mx2), p3 = pk2(mx3, mx3);                         \
            _Pragma("unroll")                                                   \
            for (int ip = 0; ip < 8; ++ip) {                                    \
                acc[0][ip] = ffma2(W[ip], p0, acc[0][ip]);                      \
                acc[1][ip] = ffma2(W[ip], p1, acc[1][ip]);                      \
                acc[2][ip] = ffma2(W[ip], p2, acc[2][ip]);                      \
                acc[3][ip] = ffma2(W[ip], p3, acc[3][ip]);                      \
            }                                                                   \
        }                                                                       \
    }

    LOAD_CHUNK(0, 0);
    LOAD_CHUNK(1, 1);
#pragma unroll 1
    for (int cn = 0; cn < 48; cn += 3) {
        LOAD_CHUNK(cn + 2, 2); COMP_CHUNK(cn, 0);
        LOAD_CHUNK(cn + 3, 0); COMP_CHUNK(cn + 1, 1);
        LOAD_CHUNK(cn + 4, 1); COMP_CHUNK(cn + 2, 2);
    }
    COMP_CHUNK(48, 0);
    COMP_CHUNK(49, 1);
#undef LOAD_CHUNK
#undef COMP_CHUNK

    // ---- diagonal correction: subtract j == t term ----
    if (tv) {
        const longlong2* wr = (const longlong2*)(sW0 + tl * W0S + t * 16);
        longlong2 q0 = wr[0], q1 = wr[1], q2 = wr[2], q3 = wr[3];
        ull W[8] = {(ull)q0.x, (ull)q0.y, (ull)q1.x, (ull)q1.y,
                    (ull)q2.x, (ull)q2.y, (ull)q3.x, (ull)q3.y};
#pragma unroll
        for (int u = 0; u < 4; ++u) {
            float md = __ldg(M + (size_t)(Bbase + u) * (D * D) + t * D + t);
            float mx = md * sX[t * 128 + bloc + u];
            ull pm = pk2(-mx, -mx);
#pragma unroll
            for (int ip = 0; ip < 8; ++ip) acc[u][ip] = ffma2(W[ip], pm, acc[u][ip]);
        }
    }

    // ---- layers 1 & 2 per owned b ----
#pragma unroll 1
    for (int u = 0; u < 4; ++u) {
        float h0f[16];
#pragma unroll
        for (int ip = 0; ip < 8; ++ip) {
            float a, b; unpk2(acc[u][ip], a, b);
            h0f[2 * ip]     = lrelu(a);
            h0f[2 * ip + 1] = lrelu(b);
        }
        float h1[16];
#pragma unroll
        for (int ii = 0; ii < 16; ++ii) {
            const float4* w1r = (const float4*)(sW1 + tl * W1S + ii * 16);
            float4 a = w1r[0], b = w1r[1], c = w1r[2], d = w1r[3];
            float s = sB1[tl * 17 + ii];
            s = fmaf(a.x, h0f[0],  s); s = fmaf(a.y, h0f[1],  s);
            s = fmaf(a.z, h0f[2],  s); s = fmaf(a.w, h0f[3],  s);
            s = fmaf(b.x, h0f[4],  s); s = fmaf(b.y, h0f[5],  s);
            s = fmaf(b.z, h0f[6],  s); s = fmaf(b.w, h0f[7],  s);
            s = fmaf(c.x, h0f[8],  s); s = fmaf(c.y, h0f[9],  s);
            s = fmaf(c.z, h0f[10], s); s = fmaf(c.w, h0f[11], s);
            s = fmaf(d.x, h0f[12], s); s = fmaf(d.y, h0f[13], s);
            s = fmaf(d.z, h0f[14], s); s = fmaf(d.w, h0f[15], s);
            h1[ii] = lrelu(s);
        }
        float po[2];
#pragma unroll
        for (int p = 0; p < 2; ++p) {
            const float4* w2r = (const float4*)(sW2 + tl * 36 + p * 16);
            float4 a = w2r[0], b = w2r[1], c = w2r[2], d = w2r[3];
            float s = sB2[tl * 2 + p];
            s = fmaf(a.x, h1[0],  s); s = fmaf(a.y, h1[1],  s);
            s = fmaf(a.z, h1[2],  s); s = fmaf(a.w, h1[3],  s);
            s = fmaf(b.x, h1[4],  s); s = fmaf(b.y, h1[5],  s);
            s = fmaf(b.z, h1[6],  s); s = fmaf(b.w, h1[7],  s);
            s = fmaf(c.x, h1[8],  s); s = fmaf(c.y, h1[9],  s);
            s = fmaf(c.z, h1[10], s); s = fmaf(c.w, h1[11], s);
            s = fmaf(d.x, h1[12], s); s = fmaf(d.y, h1[13], s);
            s = fmaf(d.z, h1[14], s); s = fmaf(d.w, h1[15], s);
            po[p] = s;
        }
        if (tv) {
            float2 o = make_float2(po[0], po[1]);
            *(float2*)(out + ((size_t)(Bbase + u) * D + t) * P) = o;
        }
    }
}

extern "C" void kernel_launch(void* const* d_in, const int* in_sizes, int n_in,
                              void* d_out, int out_size) {
    const float* x  = (const float*)d_in[0];
    const float* M  = (const float*)d_in[1];
    const float* W0 = (const float*)d_in[2];
    const float* W1 = (const float*)d_in[3];
    const float* W2 = (const float*)d_in[4];
    const float* b0 = (const float*)d_in[5];
    const float* b1 = (const float*)d_in[6];
    const float* b2 = (const float*)d_in[7];
    float* out = (float*)d_out;

    constexpr int SMEM_BYTES = SMEM_FLOATS * 4;
    cudaFuncSetAttribute(mlp_kernel, cudaFuncAttributeMaxDynamicSharedMemorySize,
                         SMEM_BYTES);

    dim3 grid((D + TB_T - 1) / TB_T, BS / TB_B);   // 13 x 128, t fast
    mlp_kernel<<<grid, NTH, SMEM_BYTES>>>(x, M, W0, W1, W2, b0, b1, b2, out);
}

// round 16
// speedup vs baseline: 1.7025x; 1.7025x over previous
#include <cuda_runtime.h>

typedef unsigned long long ull;

constexpr int BS = 16384, D = 100, H = 16, P = 2;
constexpr int DD = D * D;
constexpr int TB_B = 64;      // batch per block (8 warps x 8 b-per-thread)
constexpr int TB_T = 8;       // t per block
constexpr int NTH  = 256;     // 8 warps
constexpr int W0S  = 1616;    // sW0 row stride floats (mod 32 == 16: conflict-free phases)
constexpr int W1S  = 260;
constexpr int HS_I = 65;      // sH0 i-stride (padded)
constexpr int HS_T = 16 * HS_I;  // 1040

// smem map (float offsets)
constexpr int OFF_W0 = 0;                        // 8*1616 = 12928 (overlaid by sH0 later)
constexpr int OFF_X  = OFF_W0 + 8 * W0S;         // 12928 ; 100*64 = 6400
constexpr int OFF_W1 = OFF_X  + 6400;            // 19328 ; 2080
constexpr int OFF_B1 = OFF_W1 + 8 * W1S;         // 21408 ; 144
constexpr int OFF_W2 = OFF_B1 + 144;             // 21552 ; 288
constexpr int OFF_B2 = OFF_W2 + 288;             // 21840 ; 16
constexpr int SMEM_FLOATS = OFF_B2 + 16;         // 21856 -> 87424 B (2 CTA/SM)

__device__ __forceinline__ ull pk2(float a, float b) {
    ull r; asm("mov.b64 %0, {%1, %2};" : "=l"(r) : "f"(a), "f"(b)); return r;
}
__device__ __forceinline__ void unpk2(ull v, float& a, float& b) {
    asm("mov.b64 {%0, %1}, %2;" : "=f"(a), "=f"(b) : "l"(v));
}
__device__ __forceinline__ ull ffma2(ull a, ull b, ull c) {
    ull d; asm("fma.rn.f32x2 %0, %1, %2, %3;" : "=l"(d) : "l"(a), "l"(b), "l"(c));
    return d;
}
__device__ __forceinline__ float lrelu(float v) { return v > 0.f ? v : 0.01f * v; }

__global__ void __launch_bounds__(NTH, 2)
mlp_kernel(const float* __restrict__ xg, const float* __restrict__ M,
           const float* __restrict__ W0g, const float* __restrict__ W1g,
           const float* __restrict__ W2g, const float* __restrict__ b0g,
           const float* __restrict__ b1g, const float* __restrict__ b2g,
           float* __restrict__ out) {
    extern __shared__ float smem[];
    float* sW0 = smem + OFF_W0;
    float* sH0 = smem + OFF_W0;     // overlays sW0 after mainloop barrier
    float* sX  = smem + OFF_X;
    float* sW1 = smem + OFF_W1;
    float* sB1 = smem + OFF_B1;
    float* sW2 = smem + OFF_W2;
    float* sB2 = smem + OFF_B2;

    const int tid  = threadIdx.x;
    const int lane = tid & 31, w = tid >> 5;
    const int tl = lane >> 2, iq = lane & 3;   // 8 t-lanes x 4 i-quarters
    const int t0 = blockIdx.x * TB_T;          // t tiles on fast grid dim (L2 reuse)
    const int t  = t0 + tl;
    const bool tv = (t < D);
    const int tc = tv ? t : (D - 1);
    const int Bb = blockIdx.y * TB_B;
    const int w8 = w * 8;                      // this thread's 8 b: Bb+w8 .. +7

    // ---- stage W0 tile, transposing [t][i][j] -> sW0[r][j][i], diag col zeroed ----
    for (int e = tid; e < 4096; e += NTH) {
        int i4 = e & 3, jql = (e >> 2) & 7, jqh = (e >> 5) & 3;
        int ih = (e >> 7) & 3, r = (e >> 9) & 7;
        int jq = jql + 8 * jqh, i = i4 + 4 * ih;
        if (jq < 25) {
            int tt = t0 + r;
            float4 v = make_float4(0.f, 0.f, 0.f, 0.f);
            if (tt < D) {
                v = *(const float4*)(W0g + ((size_t)(tt * H + i)) * D + 4 * jq);
                // fold the (j != t) mask into the weights: zero column j == tt
                if ((tt >> 2) == jq) {
                    int c = tt & 3;
                    if (c == 0) v.x = 0.f;
                    else if (c == 1) v.y = 0.f;
                    else if (c == 2) v.z = 0.f;
                    else v.w = 0.f;
                }
            }
            float* dst = sW0 + r * W0S + i;
            dst[(4 * jq + 0) * 16] = v.x;
            dst[(4 * jq + 1) * 16] = v.y;
            dst[(4 * jq + 2) * 16] = v.z;
            dst[(4 * jq + 3) * 16] = v.w;
        }
    }
    // ---- stage x tile, transposing x[b][j] -> sX[j][b] ----
    for (int e = tid; e < 1600; e += NTH) {
        int b = e & 63, jq = e >> 6;           // jq 0..24
        float4 v = *(const float4*)(xg + (size_t)(Bb + b) * D + 4 * jq);
        sX[(4 * jq + 0) * 64 + b] = v.x;
        sX[(4 * jq + 1) * 64 + b] = v.y;
        sX[(4 * jq + 2) * 64 + b] = v.z;
        sX[(4 * jq + 3) * 64 + b] = v.w;
    }
    for (int e = tid; e < 8 * 256; e += NTH) {               // W1 direct copy
        int r = e >> 8, c = e & 255;
        sW1[r * W1S + c] = (t0 + r < D) ? W1g[(t0 + r) * 256 + c] : 0.f;
    }
    if (tid < 128) {
        int r = tid >> 4, c = tid & 15;
        sB1[r * 17 + c] = (t0 + r < D) ? b1g[(t0 + r) * H + c] : 0.f;
    }
    if (tid < 256) {
        int r = tid >> 5, c = tid & 31;
        sW2[r * 36 + c] = (t0 + r < D) ? W2g[(t0 + r) * (P * H) + c] : 0.f;
    }
    if (tid < 16) {
        int r = tid >> 1, c = tid & 1;
        sB2[r * 2 + c] = (t0 + r < D) ? b2g[(t0 + r) * P + c] : 0.f;
    }
    __syncthreads();

    // ---- acc init with b0: acc[u][ip], u = 8 owned b, ip = 2 i-pairs of quarter ----
    ull acc[8][2];
    {
        int ib = 4 * iq;
        float a0 = tv ? __ldg(b0g + t * H + ib)     : 0.f;
        float a1 = tv ? __ldg(b0g + t * H + ib + 1) : 0.f;
        float a2 = tv ? __ldg(b0g + t * H + ib + 2) : 0.f;
        float a3 = tv ? __ldg(b0g + t * H + ib + 3) : 0.f;
        ull p0 = pk2(a0, a1), p1 = pk2(a2, a3);
#pragma unroll
        for (int u = 0; u < 8; ++u) { acc[u][0] = p0; acc[u][1] = p1; }
    }

    const float* mp = M + (size_t)(Bb + w8) * DD + tc;   // + u*DD + j*D

    // 4-buffer register pipeline: chunk = 1 j x 8 b, prefetch distance = 3 j
    float m[4][8];

#define LOAD_J(j)                                                               \
    if ((j) < 100) {                                                            \
        const int buf = (j) & 3;                                                \
        _Pragma("unroll")                                                       \
        for (int u = 0; u < 8; ++u)                                             \
            m[buf][u] = __ldg(mp + (size_t)u * DD + (j) * D);                   \
    }

#define COMP_J(j)                                                               \
    {                                                                           \
        const int buf = (j) & 3;                                                \
        longlong2 wq = *(const longlong2*)(sW0 + tl * W0S + (j) * 16 + iq * 4); \
        ull Wa = (ull)wq.x, Wb = (ull)wq.y;                                     \
        _Pragma("unroll")                                                       \
        for (int up = 0; up < 4; ++up) {                                        \
            float2 x2 = *(const float2*)(sX + (j) * 64 + w8 + 2 * up);          \
            float mx0 = m[buf][2 * up]     * x2.x;                              \
            float mx1 = m[buf][2 * up + 1] * x2.y;                              \
            ull p0 = pk2(mx0, mx0), p1 = pk2(mx1, mx1);                         \
            acc[2 * up][0]     = ffma2(Wa, p0, acc[2 * up][0]);                 \
            acc[2 * up][1]     = ffma2(Wb, p0, acc[2 * up][1]);                 \
            acc[2 * up + 1][0] = ffma2(Wa, p1, acc[2 * up + 1][0]);             \
            acc[2 * up + 1][1] = ffma2(Wb, p1, acc[2 * up + 1][1]);             \
        }                                                                       \
    }

    LOAD_J(0); LOAD_J(1); LOAD_J(2);
#pragma unroll 1
    for (int j = 0; j < 96; j += 4) {
        LOAD_J(j + 3); COMP_J(j);
        LOAD_J(j + 4); COMP_J(j + 1);
        LOAD_J(j + 5); COMP_J(j + 2);
        LOAD_J(j + 6); COMP_J(j + 3);
    }
    LOAD_J(99);
    COMP_J(96); COMP_J(97); COMP_J(98); COMP_J(99);
#undef LOAD_J
#undef COMP_J

    // ---- exchange h0 through smem (overlay on dead sW0) ----
    __syncthreads();   // all mainloop sW0/sX reads complete
    {
        int ib = 4 * iq;
#pragma unroll
        for (int u = 0; u < 8; ++u) {
#pragma unroll
            for (int ip = 0; ip < 2; ++ip) {
                float a, b; unpk2(acc[u][ip], a, b);
                int i = ib + 2 * ip;
                sH0[tl * HS_T + i * HS_I + w8 + u]       = lrelu(a);
                sH0[tl * HS_T + (i + 1) * HS_I + w8 + u] = lrelu(b);
            }
        }
    }
    __syncthreads();

    // ---- layers 1 & 2: each thread handles 2 (t,b) pairs ----
#pragma unroll
    for (int rep = 0; rep < 2; ++rep) {
        int p = tid + rep * 256;        // 0..511
        int tloc = p >> 6, b = p & 63;
        int tg = t0 + tloc;
        float h0f[16];
#pragma unroll
        for (int i = 0; i < 16; ++i) h0f[i] = sH0[tloc * HS_T + i * HS_I + b];
        float h1[16];
#pragma unroll
        for (int ii = 0; ii < 16; ++ii) {
            const float4* w1r = (const float4*)(sW1 + tloc * W1S + ii * 16);
            float4 a = w1r[0], bb = w1r[1], c = w1r[2], d = w1r[3];
            float s = sB1[tloc * 17 + ii];
            s = fmaf(a.x,  h0f[0],  s); s = fmaf(a.y,  h0f[1],  s);
            s = fmaf(a.z,  h0f[2],  s); s = fmaf(a.w,  h0f[3],  s);
            s = fmaf(bb.x, h0f[4],  s); s = fmaf(bb.y, h0f[5],  s);
            s = fmaf(bb.z, h0f[6],  s); s = fmaf(bb.w, h0f[7],  s);
            s = fmaf(c.x,  h0f[8],  s); s = fmaf(c.y,  h0f[9],  s);
            s = fmaf(c.z,  h0f[10], s); s = fmaf(c.w,  h0f[11], s);
            s = fmaf(d.x,  h0f[12], s); s = fmaf(d.y,  h0f[13], s);
            s = fmaf(d.z,  h0f[14], s); s = fmaf(d.w,  h0f[15], s);
            h1[ii] = lrelu(s);
        }
        float po[2];
#pragma unroll
        for (int pp = 0; pp < 2; ++pp) {
            const float4* w2r = (const float4*)(sW2 + tloc * 36 + pp * 16);
            float4 a = w2r[0], bb = w2r[1], c = w2r[2], d = w2r[3];
            float s = sB2[tloc * 2 + pp];
            s = fmaf(a.x,  h1[0],  s); s = fmaf(a.y,  h1[1],  s);
            s = fmaf(a.z,  h1[2],  s); s = fmaf(a.w,  h1[3],  s);
            s = fmaf(bb.x, h1[4],  s); s = fmaf(bb.y, h1[5],  s);
            s = fmaf(bb.z, h1[6],  s); s = fmaf(bb.w, h1[7],  s);
            s = fmaf(c.x,  h1[8],  s); s = fmaf(c.y,  h1[9],  s);
            s = fmaf(c.z,  h1[10], s); s = fmaf(c.w,  h1[11], s);
            s = fmaf(d.x,  h1[12], s); s = fmaf(d.y,  h1[13], s);
            s = fmaf(d.z,  h1[14], s); s = fmaf(d.w,  h1[15], s);
            po[pp] = s;
        }
        if (tg < D) {
            float2 o = make_float2(po[0], po[1]);
            *(float2*)(out + ((size_t)(Bb + b) * D + tg) * P) = o;
        }
    }
}

extern "C" void kernel_launch(void* const* d_in, const int* in_sizes, int n_in,
                              void* d_out, int out_size) {
    const float* x  = (const float*)d_in[0];
    const float* M  = (const float*)d_in[1];
    const float* W0 = (const float*)d_in[2];
    const float* W1 = (const float*)d_in[3];
    const float* W2 = (const float*)d_in[4];
    const float* b0 = (const float*)d_in[5];
    const float* b1 = (const float*)d_in[6];
    const float* b2 = (const float*)d_in[7];
    float* out = (float*)d_out;

    constexpr int SMEM_BYTES = SMEM_FLOATS * 4;
    cudaFuncSetAttribute(mlp_kernel, cudaFuncAttributeMaxDynamicSharedMemorySize,
                         SMEM_BYTES);

    dim3 grid((D + TB_T - 1) / TB_T, BS / TB_B);   // 13 x 256, t fast
    mlp_kernel<<<grid, NTH, SMEM_BYTES>>>(x, M, W0, W1, W2, b0, b1, b2, out);
}